// round 1
// baseline (speedup 1.0000x reference)
#include <cuda_runtime.h>

#define Bsz 2
#define Ssz 256
#define Dsz 768
#define NV  765            // valid spans per batch
#define TOT 32896          // S*(S+1)/2
#define PD  128

// Scratch (device globals; no allocation allowed)
__device__ float g_H[2*Bsz*Ssz*Dsz];   // z=0: H1 = hidden@Ws1, z=1: H2 = hidden@Ws2  [z][b*S+s][D]
__device__ float g_A[2*Bsz*Ssz*Dsz];   // z=0: A1 = H1@w_p1,   z=1: A2 = H2@w_p1
__device__ float g_W3[3*Dsz];          // width_emb @ Ws3
__device__ float g_C[4*Dsz];           // rows 0..2: (W3[w]+b_span)@w_p1+b_p1 ; row 3: cpad (b_span@w_p1+b_p1)
__device__ float g_L[1028];            // [0..1023] H-row dot w_cls, [1024..1026] W3 dot, [1027] b_span.w_cls+b_cls
__device__ __align__(16) float g_projpad[PD];

// ---------------------------------------------------------------------------
// Generic tiled SGEMM: C[m,n] = sum_k A[m,k]*B[k,n].  64x64 tile, KT=16,
// 256 threads, 4x4 per thread.  All dims multiples of 64.  z-batched.
// ---------------------------------------------------------------------------
__global__ void sgemm_k(const float* __restrict__ A, long sAz,
                        const float* __restrict__ Bm, long sBz,
                        float* __restrict__ Cc, long sCz,
                        int M, int N, int K)
{
    __shared__ float As[16][65];
    __shared__ float Bs[16][64];
    A  += blockIdx.z * sAz;
    Bm += blockIdx.z * sBz;
    Cc += blockIdx.z * sCz;
    const int tx = threadIdx.x, ty = threadIdx.y;
    const int tid = ty * 16 + tx;
    const int row0 = blockIdx.y * 64, col0 = blockIdx.x * 64;

    float acc[4][4] = {};
    for (int k0 = 0; k0 < K; k0 += 16) {
        #pragma unroll
        for (int l = 0; l < 4; l++) {
            int idx = tid + l * 256;
            int m = idx >> 4, kk = idx & 15;
            As[kk][m] = A[(long)(row0 + m) * K + k0 + kk];
        }
        #pragma unroll
        for (int l = 0; l < 4; l++) {
            int idx = tid + l * 256;
            int kk = idx >> 6, n = idx & 63;
            Bs[kk][n] = Bm[(long)(k0 + kk) * N + col0 + n];
        }
        __syncthreads();
        #pragma unroll
        for (int kk = 0; kk < 16; kk++) {
            float a[4], b[4];
            #pragma unroll
            for (int u = 0; u < 4; u++) a[u] = As[kk][ty + 16 * u];
            #pragma unroll
            for (int v = 0; v < 4; v++) b[v] = Bs[kk][tx + 16 * v];
            #pragma unroll
            for (int u = 0; u < 4; u++)
                #pragma unroll
                for (int v = 0; v < 4; v++)
                    acc[u][v] += a[u] * b[v];
        }
        __syncthreads();
    }
    #pragma unroll
    for (int u = 0; u < 4; u++)
        #pragma unroll
        for (int v = 0; v < 4; v++)
            Cc[(long)(row0 + ty + 16 * u) * N + col0 + tx + 16 * v] = acc[u][v];
}

// ---------------------------------------------------------------------------
// W3[w,n] = sum_k width_emb[w,k] * w_span[2D+k, n]
// ---------------------------------------------------------------------------
__global__ void w3_k(const float* __restrict__ width_emb,
                     const float* __restrict__ w_span)
{
    int w = blockIdx.x, n = threadIdx.x;   // 3 blocks x 768 threads
    float s = 0.f;
    for (int k = 0; k < Dsz; k++)
        s += width_emb[w * Dsz + k] * w_span[(long)(2 * Dsz + k) * Dsz + n];
    g_W3[w * Dsz + n] = s;
}

// ---------------------------------------------------------------------------
// C rows: w<3 -> (W3[w]+b_span)@w_p1 + b_p1 ; w==3 -> cpad = b_span@w_p1 + b_p1
// ---------------------------------------------------------------------------
__global__ void c_k(const float* __restrict__ b_span,
                    const float* __restrict__ w_p1,
                    const float* __restrict__ b_p1)
{
    int w = blockIdx.x, d = threadIdx.x;   // 4 blocks x 768 threads
    float s = 0.f;
    for (int k = 0; k < Dsz; k++) {
        float a = b_span[k] + (w < 3 ? g_W3[w * Dsz + k] : 0.f);
        s += a * w_p1[(long)k * Dsz + d];
    }
    g_C[w * Dsz + d] = s + b_p1[d];
}

// ---------------------------------------------------------------------------
// Dot products vs w_cls: 1 warp per dot. gw<1024: g_H rows; 1024..1026: W3;
// 1027: b_span (+ b_cls).
// ---------------------------------------------------------------------------
__global__ void dots_k(const float* __restrict__ w_cls,
                       const float* __restrict__ b_cls,
                       const float* __restrict__ b_span)
{
    int gw = (blockIdx.x * blockDim.x + threadIdx.x) >> 5;
    int lane = threadIdx.x & 31;
    if (gw >= 1028) return;
    const float* v;
    if (gw < 1024)       v = g_H + (long)gw * Dsz;
    else if (gw < 1027)  v = g_W3 + (gw - 1024) * Dsz;
    else                 v = b_span;
    float s = 0.f;
    for (int k = lane; k < Dsz; k += 32) s += v[k] * w_cls[k];
    #pragma unroll
    for (int o = 16; o > 0; o >>= 1) s += __shfl_down_sync(0xffffffffu, s, o);
    if (lane == 0) g_L[gw] = s + (gw == 1027 ? b_cls[0] : 0.f);
}

// ---------------------------------------------------------------------------
// proj_pad[n] = relu(cpad) @ w_p2 + b_p2
// ---------------------------------------------------------------------------
__global__ void projpad_k(const float* __restrict__ w_p2,
                          const float* __restrict__ b_p2)
{
    int n = threadIdx.x;  // 128
    float s = 0.f;
    for (int d = 0; d < Dsz; d++)
        s += fmaxf(g_C[3 * Dsz + d], 0.f) * w_p2[(long)d * PD + n];
    g_projpad[n] = s + b_p2[n];
}

// ---------------------------------------------------------------------------
// logits for all B*TOT positions (valid formula + pad constant)
// ---------------------------------------------------------------------------
__global__ void logits_k(float* __restrict__ out)
{
    int idx = blockIdx.x * blockDim.x + threadIdx.x;
    if (idx >= Bsz * TOT) return;
    int b = idx / TOT, t = idx - b * TOT;
    float v;
    if (t < NV) {
        int i, w;
        if (t < 762)      { i = t / 3; w = t - 3 * i; }
        else if (t < 764) { i = 254;  w = t - 762;   }
        else              { i = 255;  w = 0;         }
        int j = i + w;
        v = g_L[b * Ssz + i] + g_L[512 + b * Ssz + j] + g_L[1024 + w] + g_L[1027];
    } else {
        v = g_L[1027];
    }
    out[idx] = v;
}

// ---------------------------------------------------------------------------
// Fill pad region of proj with proj_pad (float4 stores)
// ---------------------------------------------------------------------------
__global__ void fillpad_k(float* __restrict__ out)
{
    const int PADROWS = TOT - NV;                 // 32131
    long idx = blockIdx.x * (long)blockDim.x + threadIdx.x;
    if (idx >= (long)Bsz * PADROWS * 32) return;
    int r = (int)(idx >> 5), c = (int)(idx & 31);
    int b = r / PADROWS;
    int kk = NV + (r - b * PADROWS);
    float4 val = ((const float4*)g_projpad)[c];
    long f4 = (long)(Bsz * TOT) / 4 + ((long)b * TOT + kk) * (PD / 4) + c;
    ((float4*)out)[f4] = val;
}

// ---------------------------------------------------------------------------
// Valid-span projection: X[m] = relu(A1[i]+A2[j]+C[w]); out = X @ w_p2 + b_p2
// Tile: 16 spans x 128 cols, KT=16, 256 threads (32x8), 2x4 per thread.
// ---------------------------------------------------------------------------
__global__ void spanproj_k(const float* __restrict__ w_p2,
                           const float* __restrict__ b_p2,
                           float* __restrict__ out)
{
    __shared__ float Xs[16][17];
    __shared__ float Ws[16][PD];
    __shared__ int offA1[16], offA2[16], offC[16];
    __shared__ long offOut[16];

    int tid = threadIdx.x;
    int m0 = blockIdx.x * 16;
    if (tid < 16) {
        int msp = m0 + tid;
        int b = 0, i = 0, w = 0;
        bool valid = msp < 2 * NV;
        int kv = 0;
        if (valid) {
            b = msp / NV; kv = msp - b * NV;
            if (kv < 762)      { i = kv / 3; w = kv - 3 * i; }
            else if (kv < 764) { i = 254;   w = kv - 762;   }
            else               { i = 255;   w = 0;          }
        }
        int j = i + w;
        offA1[tid] = (b * Ssz + i) * Dsz;
        offA2[tid] = Bsz * Ssz * Dsz + (b * Ssz + j) * Dsz;
        offC[tid]  = w * Dsz;
        offOut[tid] = valid ? ((long)Bsz * TOT + ((long)b * TOT + kv) * PD) : -1L;
    }
    __syncthreads();

    int tx = tid & 31, ty = tid >> 5;   // 32 x 8
    float acc[2][4] = {};
    for (int k0 = 0; k0 < Dsz; k0 += 16) {
        {
            int m = tid >> 4, kk = tid & 15;
            float v = g_A[offA1[m] + k0 + kk] + g_A[offA2[m] + k0 + kk]
                    + g_C[offC[m] + k0 + kk];
            Xs[kk][m] = fmaxf(v, 0.f);
        }
        #pragma unroll
        for (int l = 0; l < 8; l++) {
            int idx = tid + l * 256;
            int kk = idx >> 7, n = idx & 127;
            Ws[kk][n] = w_p2[(long)(k0 + kk) * PD + n];
        }
        __syncthreads();
        #pragma unroll
        for (int kk = 0; kk < 16; kk++) {
            float a0 = Xs[kk][ty], a1 = Xs[kk][ty + 8];
            #pragma unroll
            for (int v = 0; v < 4; v++) {
                float bb = Ws[kk][tx + 32 * v];
                acc[0][v] += a0 * bb;
                acc[1][v] += a1 * bb;
            }
        }
        __syncthreads();
    }
    #pragma unroll
    for (int u = 0; u < 2; u++) {
        int m = ty + 8 * u;
        long ob = offOut[m];
        if (ob >= 0) {
            #pragma unroll
            for (int v = 0; v < 4; v++) {
                int n = tx + 32 * v;
                out[ob + n] = acc[u][v] + b_p2[n];
            }
        }
    }
}

// ---------------------------------------------------------------------------
extern "C" void kernel_launch(void* const* d_in, const int* in_sizes, int n_in,
                              void* d_out, int out_size)
{
    const float* hidden    = (const float*)d_in[0];
    const float* width_emb = (const float*)d_in[1];
    const float* w_span    = (const float*)d_in[2];
    const float* b_span    = (const float*)d_in[3];
    const float* w_cls     = (const float*)d_in[4];
    const float* b_cls     = (const float*)d_in[5];
    const float* w_p1      = (const float*)d_in[6];
    const float* b_p1      = (const float*)d_in[7];
    const float* w_p2      = (const float*)d_in[8];
    const float* b_p2      = (const float*)d_in[9];
    float* out = (float*)d_out;

    float *pH = nullptr, *pA = nullptr;
    cudaGetSymbolAddress((void**)&pH, g_H);
    cudaGetSymbolAddress((void**)&pA, g_A);

    // W3 (independent)
    w3_k<<<3, Dsz>>>(width_emb, w_span);

    // H1,H2 = hidden @ w_span[zD:(z+1)D]   (M=512, N=768, K=768, z=2)
    sgemm_k<<<dim3(Dsz / 64, (Bsz * Ssz) / 64, 2), dim3(16, 16)>>>(
        hidden, 0L, w_span, (long)Dsz * Dsz, pH, (long)Bsz * Ssz * Dsz,
        Bsz * Ssz, Dsz, Dsz);

    // A1,A2 = H{1,2} @ w_p1
    sgemm_k<<<dim3(Dsz / 64, (Bsz * Ssz) / 64, 2), dim3(16, 16)>>>(
        pH, (long)Bsz * Ssz * Dsz, w_p1, 0L, pA, (long)Bsz * Ssz * Dsz,
        Bsz * Ssz, Dsz, Dsz);

    // C rows (needs W3)
    c_k<<<4, Dsz>>>(b_span, w_p1, b_p1);

    // classifier dots (needs H, W3)
    dots_k<<<129, 256>>>(w_cls, b_cls, b_span);

    // proj pad vector (needs C)
    projpad_k<<<1, PD>>>(w_p2, b_p2);

    // logits: full B*TOT (needs dots)
    logits_k<<<(Bsz * TOT + 255) / 256, 256>>>(out);

    // pad fill for proj (needs projpad)
    {
        long n = (long)Bsz * (TOT - NV) * 32;
        fillpad_k<<<(int)((n + 255) / 256), 256>>>(out);
    }

    // valid span projection (needs A, C)
    spanproj_k<<<(2 * NV + 15) / 16, 256>>>(w_p2, b_p2, out);
}

// round 2
// speedup vs baseline: 1.6997x; 1.6997x over previous
#include <cuda_runtime.h>

#define Bsz 2
#define Ssz 256
#define Dsz 768
#define NV  765            // valid spans per batch
#define TOT 32896          // S*(S+1)/2
#define PD  128

typedef unsigned long long ull;

// Scratch (device globals; no allocation allowed)
__device__ float g_H[2*Bsz*Ssz*Dsz];   // z=0: H1 = hidden@Ws1, z=1: H2 = hidden@Ws2
__device__ float g_A[2*Bsz*Ssz*Dsz];   // z=0: A1 = H1@w_p1,   z=1: A2 = H2@w_p1
__device__ float g_W3[3*Dsz];          // width_emb @ Ws3
__device__ float g_C[4*Dsz];           // rows 0..2: (W3[w]+b_span)@w_p1+b_p1 ; row 3: cpad
__device__ float g_L[1028];            // [0..1023] H-row dot w_cls, [1024..1026] W3 dot, [1027] b_span.w_cls+b_cls
__device__ __align__(16) float g_projpad[PD];

// ---------------------------------------------------------------------------
__device__ __forceinline__ ull pk2(float x) {
    ull r; asm("mov.b64 %0, {%1, %1};" : "=l"(r) : "f"(x)); return r;
}
__device__ __forceinline__ void fma2(ull& d, ull a, ull b) {
    asm("fma.rn.f32x2 %0, %1, %2, %0;" : "+l"(d) : "l"(a), "l"(b));
}

// ---------------------------------------------------------------------------
// Tiled SGEMM with packed f32x2 FMA: C[m,n] = sum_k A[m,k]*B[k,n]
// Tile 64(M) x 128(N), KT=16, 256 threads, 4 rows x 8 cols (4x4 f32x2)/thread.
// M mult of 64, N mult of 128, K mult of 16.  z-batched.
// ---------------------------------------------------------------------------
__global__ void sgemm_k(const float* __restrict__ A, long sAz,
                        const float* __restrict__ Bm, long sBz,
                        float* __restrict__ Cc, long sCz,
                        int M, int N, int K)
{
    __shared__ float As[16][65];
    __shared__ float Bs[16][128];
    A  += blockIdx.z * sAz;
    Bm += blockIdx.z * sBz;
    Cc += blockIdx.z * sCz;
    const int tx = threadIdx.x, ty = threadIdx.y;
    const int tid = ty * 16 + tx;
    const int row0 = blockIdx.y * 64, col0 = blockIdx.x * 128;

    ull acc[4][4] = {};
    for (int k0 = 0; k0 < K; k0 += 16) {
        #pragma unroll
        for (int l = 0; l < 4; l++) {
            int idx = tid + l * 256;
            int m = idx >> 4, kk = idx & 15;
            As[kk][m] = A[(long)(row0 + m) * K + k0 + kk];
        }
        #pragma unroll
        for (int l = 0; l < 8; l++) {
            int idx = tid + l * 256;
            int kk = idx >> 7, n = idx & 127;
            Bs[kk][n] = Bm[(long)(k0 + kk) * N + col0 + n];
        }
        __syncthreads();
        #pragma unroll
        for (int kk = 0; kk < 16; kk++) {
            ull aa[4];
            #pragma unroll
            for (int u = 0; u < 4; u++) aa[u] = pk2(As[kk][ty + 16 * u]);
            const ull* brow = (const ull*)&Bs[kk][0];
            #pragma unroll
            for (int v = 0; v < 4; v++) {
                ull bb = brow[tx + 16 * v];
                #pragma unroll
                for (int u = 0; u < 4; u++) fma2(acc[u][v], aa[u], bb);
            }
        }
        __syncthreads();
    }
    #pragma unroll
    for (int u = 0; u < 4; u++) {
        long rbase = ((long)(row0 + ty + 16 * u) * N + col0) >> 1;
        #pragma unroll
        for (int v = 0; v < 4; v++) {
            float2 r;
            asm("mov.b64 {%0, %1}, %2;" : "=f"(r.x), "=f"(r.y) : "l"(acc[u][v]));
            ((float2*)Cc)[rbase + tx + 16 * v] = r;
        }
    }
}

// ---------------------------------------------------------------------------
// Init: zero g_W3, g_C <- b_p1 bias, g_projpad <- b_p2
// ---------------------------------------------------------------------------
__global__ void init_k(const float* __restrict__ b_p1,
                       const float* __restrict__ b_p2)
{
    int i = blockIdx.x * 256 + threadIdx.x;
    if (i < 3 * Dsz) g_W3[i] = 0.f;
    else if (i < 3 * Dsz + 4 * Dsz) {
        int j = i - 3 * Dsz;
        g_C[j] = b_p1[j - (j / Dsz) * Dsz];
    } else if (i < 3 * Dsz + 4 * Dsz + PD) {
        int j = i - 7 * Dsz;
        g_projpad[j] = b_p2[j];
    }
}

// ---------------------------------------------------------------------------
// K-split GEMV accumulators (atomicAdd into pre-initialized outputs)
// grid(ncols/64, 8, M), 256 threads = 64 cols x 4 k-subgroups, 24 k/thread.
// ---------------------------------------------------------------------------
__global__ void w3acc_k(const float* __restrict__ we,
                        const float* __restrict__ w_span)
{
    __shared__ float red[4][64];
    int m = blockIdx.z;
    int nl = threadIdx.x & 63, kg = threadIdx.x >> 6;
    int n = blockIdx.x * 64 + nl;
    int k0 = blockIdx.y * 96 + kg * 24;
    const float* Wt = w_span + 2L * Dsz * Dsz;
    float s = 0.f;
    #pragma unroll
    for (int t = 0; t < 24; t++) {
        int k = k0 + t;
        s += we[m * Dsz + k] * Wt[(long)k * Dsz + n];
    }
    red[kg][nl] = s;
    __syncthreads();
    if (kg == 0)
        atomicAdd(&g_W3[m * Dsz + n],
                  red[0][nl] + red[1][nl] + red[2][nl] + red[3][nl]);
}

__global__ void cacc_k(const float* __restrict__ b_span,
                       const float* __restrict__ w_p1)
{
    __shared__ float red[4][64];
    int m = blockIdx.z;
    int nl = threadIdx.x & 63, kg = threadIdx.x >> 6;
    int n = blockIdx.x * 64 + nl;
    int k0 = blockIdx.y * 96 + kg * 24;
    float s = 0.f;
    #pragma unroll
    for (int t = 0; t < 24; t++) {
        int k = k0 + t;
        float a = b_span[k] + (m < 3 ? g_W3[m * Dsz + k] : 0.f);
        s += a * w_p1[(long)k * Dsz + n];
    }
    red[kg][nl] = s;
    __syncthreads();
    if (kg == 0)
        atomicAdd(&g_C[m * Dsz + n],
                  red[0][nl] + red[1][nl] + red[2][nl] + red[3][nl]);
}

__global__ void ppacc_k(const float* __restrict__ w_p2)
{
    __shared__ float red[4][64];
    int nl = threadIdx.x & 63, kg = threadIdx.x >> 6;
    int n = blockIdx.x * 64 + nl;
    int k0 = blockIdx.y * 96 + kg * 24;
    float s = 0.f;
    #pragma unroll
    for (int t = 0; t < 24; t++) {
        int k = k0 + t;
        s += fmaxf(g_C[3 * Dsz + k], 0.f) * w_p2[(long)k * PD + n];
    }
    red[kg][nl] = s;
    __syncthreads();
    if (kg == 0)
        atomicAdd(&g_projpad[n],
                  red[0][nl] + red[1][nl] + red[2][nl] + red[3][nl]);
}

// ---------------------------------------------------------------------------
// Dot products vs w_cls: 1 warp per dot.
// ---------------------------------------------------------------------------
__global__ void dots_k(const float* __restrict__ w_cls,
                       const float* __restrict__ b_cls,
                       const float* __restrict__ b_span)
{
    int gw = (blockIdx.x * blockDim.x + threadIdx.x) >> 5;
    int lane = threadIdx.x & 31;
    if (gw >= 1028) return;
    const float* v;
    if (gw < 1024)       v = g_H + (long)gw * Dsz;
    else if (gw < 1027)  v = g_W3 + (gw - 1024) * Dsz;
    else                 v = b_span;
    float s = 0.f;
    for (int k = lane; k < Dsz; k += 32) s += v[k] * w_cls[k];
    #pragma unroll
    for (int o = 16; o > 0; o >>= 1) s += __shfl_down_sync(0xffffffffu, s, o);
    if (lane == 0) g_L[gw] = s + (gw == 1027 ? b_cls[0] : 0.f);
}

// ---------------------------------------------------------------------------
// logits for all B*TOT positions
// ---------------------------------------------------------------------------
__global__ void logits_k(float* __restrict__ out)
{
    int idx = blockIdx.x * blockDim.x + threadIdx.x;
    if (idx >= Bsz * TOT) return;
    int b = idx / TOT, t = idx - b * TOT;
    float v;
    if (t < NV) {
        int i, w;
        if (t < 762)      { i = t / 3; w = t - 3 * i; }
        else if (t < 764) { i = 254;  w = t - 762;   }
        else              { i = 255;  w = 0;         }
        int j = i + w;
        v = g_L[b * Ssz + i] + g_L[512 + b * Ssz + j] + g_L[1024 + w] + g_L[1027];
    } else {
        v = g_L[1027];
    }
    out[idx] = v;
}

// ---------------------------------------------------------------------------
// Fill pad region of proj with proj_pad (float4 stores)
// ---------------------------------------------------------------------------
__global__ void fillpad_k(float* __restrict__ out)
{
    const int PADROWS = TOT - NV;                 // 32131
    long idx = blockIdx.x * (long)blockDim.x + threadIdx.x;
    if (idx >= (long)Bsz * PADROWS * 32) return;
    int r = (int)(idx >> 5), c = (int)(idx & 31);
    int b = r / PADROWS;
    int kk = NV + (r - b * PADROWS);
    float4 val = ((const float4*)g_projpad)[c];
    long f4 = (long)(Bsz * TOT) / 4 + ((long)b * TOT + kk) * (PD / 4) + c;
    ((float4*)out)[f4] = val;
}

// ---------------------------------------------------------------------------
// Valid-span projection: X[m] = relu(A1[i]+A2[j]+C[w]); out = X @ w_p2 + b_p2
// ---------------------------------------------------------------------------
__global__ void spanproj_k(const float* __restrict__ w_p2,
                           const float* __restrict__ b_p2,
                           float* __restrict__ out)
{
    __shared__ float Xs[16][17];
    __shared__ float Ws[16][PD];
    __shared__ int offA1[16], offA2[16], offC[16];
    __shared__ long offOut[16];

    int tid = threadIdx.x;
    int m0 = blockIdx.x * 16;
    if (tid < 16) {
        int msp = m0 + tid;
        int b = 0, i = 0, w = 0;
        bool valid = msp < 2 * NV;
        int kv = 0;
        if (valid) {
            b = msp / NV; kv = msp - b * NV;
            if (kv < 762)      { i = kv / 3; w = kv - 3 * i; }
            else if (kv < 764) { i = 254;   w = kv - 762;   }
            else               { i = 255;   w = 0;          }
        }
        int j = i + w;
        offA1[tid] = (b * Ssz + i) * Dsz;
        offA2[tid] = Bsz * Ssz * Dsz + (b * Ssz + j) * Dsz;
        offC[tid]  = w * Dsz;
        offOut[tid] = valid ? ((long)Bsz * TOT + ((long)b * TOT + kv) * PD) : -1L;
    }
    __syncthreads();

    int tx = tid & 31, ty = tid >> 5;   // 32 x 8
    float acc[2][4] = {};
    for (int k0 = 0; k0 < Dsz; k0 += 16) {
        {
            int m = tid >> 4, kk = tid & 15;
            float v = g_A[offA1[m] + k0 + kk] + g_A[offA2[m] + k0 + kk]
                    + g_C[offC[m] + k0 + kk];
            Xs[kk][m] = fmaxf(v, 0.f);
        }
        #pragma unroll
        for (int l = 0; l < 8; l++) {
            int idx = tid + l * 256;
            int kk = idx >> 7, n = idx & 127;
            Ws[kk][n] = w_p2[(long)(k0 + kk) * PD + n];
        }
        __syncthreads();
        #pragma unroll
        for (int kk = 0; kk < 16; kk++) {
            float a0 = Xs[kk][ty], a1 = Xs[kk][ty + 8];
            #pragma unroll
            for (int v = 0; v < 4; v++) {
                float bb = Ws[kk][tx + 32 * v];
                acc[0][v] += a0 * bb;
                acc[1][v] += a1 * bb;
            }
        }
        __syncthreads();
    }
    #pragma unroll
    for (int u = 0; u < 2; u++) {
        int m = ty + 8 * u;
        long ob = offOut[m];
        if (ob >= 0) {
            #pragma unroll
            for (int v = 0; v < 4; v++) {
                int n = tx + 32 * v;
                out[ob + n] = acc[u][v] + b_p2[n];
            }
        }
    }
}

// ---------------------------------------------------------------------------
extern "C" void kernel_launch(void* const* d_in, const int* in_sizes, int n_in,
                              void* d_out, int out_size)
{
    const float* hidden    = (const float*)d_in[0];
    const float* width_emb = (const float*)d_in[1];
    const float* w_span    = (const float*)d_in[2];
    const float* b_span    = (const float*)d_in[3];
    const float* w_cls     = (const float*)d_in[4];
    const float* b_cls     = (const float*)d_in[5];
    const float* w_p1      = (const float*)d_in[6];
    const float* b_p1      = (const float*)d_in[7];
    const float* w_p2      = (const float*)d_in[8];
    const float* b_p2      = (const float*)d_in[9];
    float* out = (float*)d_out;

    float *pH = nullptr, *pA = nullptr;
    cudaGetSymbolAddress((void**)&pH, g_H);
    cudaGetSymbolAddress((void**)&pA, g_A);

    // init biases / zeros for atomic accumulators
    init_k<<<22, 256>>>(b_p1, b_p2);

    // W3 = width_emb @ Ws3  (k-split accumulate)
    w3acc_k<<<dim3(12, 8, 3), 256>>>(width_emb, w_span);

    // H1,H2 = hidden @ w_span[zD:(z+1)D]   (M=512, N=768, K=768, z=2)
    sgemm_k<<<dim3(Dsz / 128, (Bsz * Ssz) / 64, 2), dim3(16, 16)>>>(
        hidden, 0L, w_span, (long)Dsz * Dsz, pH, (long)Bsz * Ssz * Dsz,
        Bsz * Ssz, Dsz, Dsz);

    // A1,A2 = H{1,2} @ w_p1
    sgemm_k<<<dim3(Dsz / 128, (Bsz * Ssz) / 64, 2), dim3(16, 16)>>>(
        pH, (long)Bsz * Ssz * Dsz, w_p1, 0L, pA, (long)Bsz * Ssz * Dsz,
        Bsz * Ssz, Dsz, Dsz);

    // C rows (needs W3 + init)
    cacc_k<<<dim3(12, 8, 4), 256>>>(b_span, w_p1);

    // classifier dots (needs H, W3)
    dots_k<<<129, 256>>>(w_cls, b_cls, b_span);

    // proj pad vector (needs C)
    ppacc_k<<<dim3(2, 8, 1), 256>>>(w_p2);

    // logits: full B*TOT (needs dots)
    logits_k<<<(Bsz * TOT + 255) / 256, 256>>>(out);

    // pad fill for proj (needs projpad)
    {
        long n = (long)Bsz * (TOT - NV) * 32;
        fillpad_k<<<(int)((n + 255) / 256), 256>>>(out);
    }

    // valid span projection (needs A, C)
    spanproj_k<<<(2 * NV + 15) / 16, 256>>>(w_p2, b_p2, out);
}

// round 3
// speedup vs baseline: 2.0840x; 1.2261x over previous
#include <cuda_runtime.h>

#define Bsz 2
#define Ssz 256
#define Dsz 768
#define NV  765            // valid spans per batch
#define TOT 32896          // S*(S+1)/2
#define PD  128
#define KSPLIT 3
#define KH  256            // 768 / KSPLIT
#define HS  393216L        // Bsz*Ssz*Dsz

typedef unsigned long long ull;

// Scratch (device globals; no allocation allowed)
// Layout of g_H/g_A: [ks (3)][z (2)][row (512)][n (768)] — partial K sums
__device__ float g_H[3 * 2 * Bsz * Ssz * Dsz];
__device__ float g_A[3 * 2 * Bsz * Ssz * Dsz];
__device__ float g_W3[3*Dsz];          // width_emb @ Ws3
__device__ float g_C[4*Dsz];           // 0..2: (W3[w]+b_span)@w_p1+b_p1 ; 3: cpad
__device__ float g_L[1028];
__device__ __align__(16) float g_projpad[PD];

// ---------------------------------------------------------------------------
__device__ __forceinline__ ull pk2(float x) {
    ull r; asm("mov.b64 %0, {%1, %1};" : "=l"(r) : "f"(x)); return r;
}
__device__ __forceinline__ void fma2(ull& d, ull a, ull b) {
    asm("fma.rn.f32x2 %0, %1, %2, %0;" : "+l"(d) : "l"(a), "l"(b));
}

// ---------------------------------------------------------------------------
// K-split tiled SGEMM, packed f32x2 FMA.  C_partial[ks][z] = A[z] @ B[z] over
// K-range [ks*KH, (ks+1)*KH).  Tile 64(M) x 128(N), KT=16, 256 threads,
// per-thread 4 rows x 8 cols (4x4 f32x2).  A optionally summed from 3 bufs.
// grid = (N/128, M/64, 2*KSPLIT)
// ---------------------------------------------------------------------------
__global__ void sgemm_k(const float* __restrict__ A,
                        const float* __restrict__ Ax1,
                        const float* __restrict__ Ax2, long sAz,
                        const float* __restrict__ Bm, long sBz,
                        float* __restrict__ Cc, long sCz, long sCk)
{
    __shared__ float As[16][65];
    __shared__ __align__(16) float Bs[16][128];

    const int zi = blockIdx.z;
    const int z  = zi / KSPLIT;
    const int ks = zi % KSPLIT;
    const int kbase = ks * KH;

    A  += (long)z * sAz;
    if (Ax1) { Ax1 += (long)z * sAz; Ax2 += (long)z * sAz; }
    Bm += (long)z * sBz;
    Cc += (long)z * sCz + (long)ks * sCk;

    const int tx = threadIdx.x, ty = threadIdx.y;
    const int tid = ty * 16 + tx;
    const int row0 = blockIdx.y * 64, col0 = blockIdx.x * 128;

    // load assignments
    const int m_a = tid >> 2, kq = tid & 3;            // A: row m_a, float4 col kq
    const int kk0 = tid >> 5, nq0 = tid & 31;          // B: rows kk0 and kk0+8

    ull acc[4][4] = {};
    float4 pa, pb0, pb1;

    // prefetch iter 0
    {
        long ab = (long)(row0 + m_a) * Dsz + kbase + kq * 4;
        pa = *(const float4*)(A + ab);
        if (Ax1) {
            float4 q1 = *(const float4*)(Ax1 + ab);
            float4 q2 = *(const float4*)(Ax2 + ab);
            pa.x += q1.x + q2.x; pa.y += q1.y + q2.y;
            pa.z += q1.z + q2.z; pa.w += q1.w + q2.w;
        }
        pb0 = *(const float4*)(Bm + (long)(kbase + kk0) * Dsz + col0 + nq0 * 4);
        pb1 = *(const float4*)(Bm + (long)(kbase + kk0 + 8) * Dsz + col0 + nq0 * 4);
    }

    const int ITERS = KH / 16;   // 16
    for (int it = 0; it < ITERS; it++) {
        __syncthreads();
        As[kq * 4 + 0][m_a] = pa.x;
        As[kq * 4 + 1][m_a] = pa.y;
        As[kq * 4 + 2][m_a] = pa.z;
        As[kq * 4 + 3][m_a] = pa.w;
        ((float4*)&Bs[kk0][0])[nq0]     = pb0;
        ((float4*)&Bs[kk0 + 8][0])[nq0] = pb1;
        __syncthreads();

        if (it + 1 < ITERS) {
            int kb = kbase + (it + 1) * 16;
            long ab = (long)(row0 + m_a) * Dsz + kb + kq * 4;
            pa = *(const float4*)(A + ab);
            if (Ax1) {
                float4 q1 = *(const float4*)(Ax1 + ab);
                float4 q2 = *(const float4*)(Ax2 + ab);
                pa.x += q1.x + q2.x; pa.y += q1.y + q2.y;
                pa.z += q1.z + q2.z; pa.w += q1.w + q2.w;
            }
            pb0 = *(const float4*)(Bm + (long)(kb + kk0) * Dsz + col0 + nq0 * 4);
            pb1 = *(const float4*)(Bm + (long)(kb + kk0 + 8) * Dsz + col0 + nq0 * 4);
        }

        #pragma unroll
        for (int kk = 0; kk < 16; kk++) {
            ull aa[4];
            #pragma unroll
            for (int u = 0; u < 4; u++) aa[u] = pk2(As[kk][ty + 16 * u]);
            const ull* brow = (const ull*)&Bs[kk][0];
            #pragma unroll
            for (int v = 0; v < 4; v++) {
                ull bb = brow[tx + 16 * v];
                #pragma unroll
                for (int u = 0; u < 4; u++) fma2(acc[u][v], aa[u], bb);
            }
        }
    }

    #pragma unroll
    for (int u = 0; u < 4; u++) {
        long rbase = ((long)(row0 + ty + 16 * u) * Dsz + col0) >> 1;
        #pragma unroll
        for (int v = 0; v < 4; v++) {
            float2 r;
            asm("mov.b64 {%0, %1}, %2;" : "=f"(r.x), "=f"(r.y) : "l"(acc[u][v]));
            ((float2*)Cc)[rbase + tx + 16 * v] = r;
        }
    }
}

// ---------------------------------------------------------------------------
// Init: zero g_W3, g_C <- b_p1 bias, g_projpad <- b_p2
// ---------------------------------------------------------------------------
__global__ void init_k(const float* __restrict__ b_p1,
                       const float* __restrict__ b_p2)
{
    int i = blockIdx.x * 256 + threadIdx.x;
    if (i < 3 * Dsz) g_W3[i] = 0.f;
    else if (i < 3 * Dsz + 4 * Dsz) {
        int j = i - 3 * Dsz;
        g_C[j] = b_p1[j - (j / Dsz) * Dsz];
    } else if (i < 3 * Dsz + 4 * Dsz + PD) {
        int j = i - 7 * Dsz;
        g_projpad[j] = b_p2[j];
    }
}

// ---------------------------------------------------------------------------
// K-split GEMV accumulators (atomicAdd into pre-initialized outputs)
// ---------------------------------------------------------------------------
__global__ void w3acc_k(const float* __restrict__ we,
                        const float* __restrict__ w_span)
{
    __shared__ float red[4][64];
    int m = blockIdx.z;
    int nl = threadIdx.x & 63, kg = threadIdx.x >> 6;
    int n = blockIdx.x * 64 + nl;
    int k0 = blockIdx.y * 96 + kg * 24;
    const float* Wt = w_span + 2L * Dsz * Dsz;
    float s = 0.f;
    #pragma unroll
    for (int t = 0; t < 24; t++) {
        int k = k0 + t;
        s += we[m * Dsz + k] * Wt[(long)k * Dsz + n];
    }
    red[kg][nl] = s;
    __syncthreads();
    if (kg == 0)
        atomicAdd(&g_W3[m * Dsz + n],
                  red[0][nl] + red[1][nl] + red[2][nl] + red[3][nl]);
}

__global__ void cacc_k(const float* __restrict__ b_span,
                       const float* __restrict__ w_p1)
{
    __shared__ float red[4][64];
    int m = blockIdx.z;
    int nl = threadIdx.x & 63, kg = threadIdx.x >> 6;
    int n = blockIdx.x * 64 + nl;
    int k0 = blockIdx.y * 96 + kg * 24;
    float s = 0.f;
    #pragma unroll
    for (int t = 0; t < 24; t++) {
        int k = k0 + t;
        float a = b_span[k] + (m < 3 ? g_W3[m * Dsz + k] : 0.f);
        s += a * w_p1[(long)k * Dsz + n];
    }
    red[kg][nl] = s;
    __syncthreads();
    if (kg == 0)
        atomicAdd(&g_C[m * Dsz + n],
                  red[0][nl] + red[1][nl] + red[2][nl] + red[3][nl]);
}

__global__ void ppacc_k(const float* __restrict__ w_p2)
{
    __shared__ float red[4][64];
    int nl = threadIdx.x & 63, kg = threadIdx.x >> 6;
    int n = blockIdx.x * 64 + nl;
    int k0 = blockIdx.y * 96 + kg * 24;
    float s = 0.f;
    #pragma unroll
    for (int t = 0; t < 24; t++) {
        int k = k0 + t;
        s += fmaxf(g_C[3 * Dsz + k], 0.f) * w_p2[(long)k * PD + n];
    }
    red[kg][nl] = s;
    __syncthreads();
    if (kg == 0)
        atomicAdd(&g_projpad[n],
                  red[0][nl] + red[1][nl] + red[2][nl] + red[3][nl]);
}

// ---------------------------------------------------------------------------
// Dot products vs w_cls: 1 warp per dot (H rows sum 3 K-partials)
// ---------------------------------------------------------------------------
__global__ void dots_k(const float* __restrict__ w_cls,
                       const float* __restrict__ b_cls,
                       const float* __restrict__ b_span)
{
    int gw = (blockIdx.x * blockDim.x + threadIdx.x) >> 5;
    int lane = threadIdx.x & 31;
    if (gw >= 1028) return;
    float s = 0.f;
    if (gw < 1024) {
        int z = gw >> 9, row = gw & 511;
        const float* base = g_H + (long)z * HS + (long)row * Dsz;
        for (int k = lane; k < Dsz; k += 32)
            s += (base[k] + base[2 * HS + k] + base[4 * HS + k]) * w_cls[k];
    } else {
        const float* v = (gw < 1027) ? (g_W3 + (gw - 1024) * Dsz) : b_span;
        for (int k = lane; k < Dsz; k += 32) s += v[k] * w_cls[k];
    }
    #pragma unroll
    for (int o = 16; o > 0; o >>= 1) s += __shfl_down_sync(0xffffffffu, s, o);
    if (lane == 0) g_L[gw] = s + (gw == 1027 ? b_cls[0] : 0.f);
}

// ---------------------------------------------------------------------------
// logits for all B*TOT positions
// ---------------------------------------------------------------------------
__global__ void logits_k(float* __restrict__ out)
{
    int idx = blockIdx.x * blockDim.x + threadIdx.x;
    if (idx >= Bsz * TOT) return;
    int b = idx / TOT, t = idx - b * TOT;
    float v;
    if (t < NV) {
        int i, w;
        if (t < 762)      { i = t / 3; w = t - 3 * i; }
        else if (t < 764) { i = 254;  w = t - 762;   }
        else              { i = 255;  w = 0;         }
        int j = i + w;
        v = g_L[b * Ssz + i] + g_L[512 + b * Ssz + j] + g_L[1024 + w] + g_L[1027];
    } else {
        v = g_L[1027];
    }
    out[idx] = v;
}

// ---------------------------------------------------------------------------
// Fill pad region of proj with proj_pad (float4 stores)
// ---------------------------------------------------------------------------
__global__ void fillpad_k(float* __restrict__ out)
{
    const int PADROWS = TOT - NV;                 // 32131
    long idx = blockIdx.x * (long)blockDim.x + threadIdx.x;
    if (idx >= (long)Bsz * PADROWS * 32) return;
    int r = (int)(idx >> 5), c = (int)(idx & 31);
    int b = r / PADROWS;
    int kk = NV + (r - b * PADROWS);
    float4 val = ((const float4*)g_projpad)[c];
    long f4 = (long)(Bsz * TOT) / 4 + ((long)b * TOT + kk) * (PD / 4) + c;
    ((float4*)out)[f4] = val;
}

// ---------------------------------------------------------------------------
// Valid-span projection: X[m] = relu(A1[i]+A2[j]+C[w]); out = X @ w_p2 + b_p2
// A rows summed from 3 K-partials.
// ---------------------------------------------------------------------------
__global__ void spanproj_k(const float* __restrict__ w_p2,
                           const float* __restrict__ b_p2,
                           float* __restrict__ out)
{
    __shared__ float Xs[16][17];
    __shared__ float Ws[16][PD];
    __shared__ int offA1[16], offA2[16], offC[16];
    __shared__ long offOut[16];

    int tid = threadIdx.x;
    int m0 = blockIdx.x * 16;
    if (tid < 16) {
        int msp = m0 + tid;
        int b = 0, i = 0, w = 0;
        bool valid = msp < 2 * NV;
        int kv = 0;
        if (valid) {
            b = msp / NV; kv = msp - b * NV;
            if (kv < 762)      { i = kv / 3; w = kv - 3 * i; }
            else if (kv < 764) { i = 254;   w = kv - 762;   }
            else               { i = 255;   w = 0;          }
        }
        int j = i + w;
        offA1[tid] = (b * Ssz + i) * Dsz;                 // z=0 region
        offA2[tid] = (int)HS + (b * Ssz + j) * Dsz;       // z=1 region
        offC[tid]  = w * Dsz;
        offOut[tid] = valid ? ((long)Bsz * TOT + ((long)b * TOT + kv) * PD) : -1L;
    }
    __syncthreads();

    int tx = tid & 31, ty = tid >> 5;   // 32 x 8
    float acc[2][4] = {};
    for (int k0 = 0; k0 < Dsz; k0 += 16) {
        {
            int m = tid >> 4, kk = tid & 15;
            long o1 = offA1[m] + k0 + kk, o2 = offA2[m] + k0 + kk;
            float v = g_A[o1] + g_A[o1 + 2 * HS] + g_A[o1 + 4 * HS]
                    + g_A[o2] + g_A[o2 + 2 * HS] + g_A[o2 + 4 * HS]
                    + g_C[offC[m] + k0 + kk];
            Xs[kk][m] = fmaxf(v, 0.f);
        }
        #pragma unroll
        for (int l = 0; l < 8; l++) {
            int idx = tid + l * 256;
            int kk = idx >> 7, n = idx & 127;
            Ws[kk][n] = w_p2[(long)(k0 + kk) * PD + n];
        }
        __syncthreads();
        #pragma unroll
        for (int kk = 0; kk < 16; kk++) {
            float a0 = Xs[kk][ty], a1 = Xs[kk][ty + 8];
            #pragma unroll
            for (int v = 0; v < 4; v++) {
                float bb = Ws[kk][tx + 32 * v];
                acc[0][v] += a0 * bb;
                acc[1][v] += a1 * bb;
            }
        }
        __syncthreads();
    }
    #pragma unroll
    for (int u = 0; u < 2; u++) {
        int m = ty + 8 * u;
        long ob = offOut[m];
        if (ob >= 0) {
            #pragma unroll
            for (int v = 0; v < 4; v++) {
                int n = tx + 32 * v;
                out[ob + n] = acc[u][v] + b_p2[n];
            }
        }
    }
}

// ---------------------------------------------------------------------------
extern "C" void kernel_launch(void* const* d_in, const int* in_sizes, int n_in,
                              void* d_out, int out_size)
{
    const float* hidden    = (const float*)d_in[0];
    const float* width_emb = (const float*)d_in[1];
    const float* w_span    = (const float*)d_in[2];
    const float* b_span    = (const float*)d_in[3];
    const float* w_cls     = (const float*)d_in[4];
    const float* b_cls     = (const float*)d_in[5];
    const float* w_p1      = (const float*)d_in[6];
    const float* b_p1      = (const float*)d_in[7];
    const float* w_p2      = (const float*)d_in[8];
    const float* b_p2      = (const float*)d_in[9];
    float* out = (float*)d_out;

    float *pH = nullptr, *pA = nullptr;
    cudaGetSymbolAddress((void**)&pH, g_H);
    cudaGetSymbolAddress((void**)&pA, g_A);

    // init biases / zeros for atomic accumulators
    init_k<<<22, 256>>>(b_p1, b_p2);

    // W3 = width_emb @ Ws3  (k-split accumulate)
    w3acc_k<<<dim3(12, 8, 3), 256>>>(width_emb, w_span);

    // C rows (needs W3 + init)
    cacc_k<<<dim3(12, 8, 4), 256>>>(b_span, w_p1);

    // proj pad vector (needs C)
    ppacc_k<<<dim3(2, 8, 1), 256>>>(w_p2);

    // H partials = hidden @ w_span[zD:(z+1)D]  (M=512,N=768, K-split 3, z=2)
    sgemm_k<<<dim3(6, 8, 6), dim3(16, 16)>>>(
        hidden, nullptr, nullptr, 0L, w_span, (long)Dsz * Dsz,
        pH, HS, 2 * HS);

    // classifier dots (needs H)
    dots_k<<<129, 256>>>(w_cls, b_cls, b_span);

    // A partials = (sum H partials) @ w_p1
    sgemm_k<<<dim3(6, 8, 6), dim3(16, 16)>>>(
        pH, pH + 2 * HS, pH + 4 * HS, HS, w_p1, 0L,
        pA, HS, 2 * HS);

    // logits: full B*TOT (needs dots)
    logits_k<<<(Bsz * TOT + 255) / 256, 256>>>(out);

    // pad fill for proj (needs projpad)
    {
        long n = (long)Bsz * (TOT - NV) * 32;
        fillpad_k<<<(int)((n + 255) / 256), 256>>>(out);
    }

    // valid span projection (needs A, C)
    spanproj_k<<<(2 * NV + 15) / 16, 256>>>(w_p2, b_p2, out);
}

// round 4
// speedup vs baseline: 2.5553x; 1.2261x over previous
#include <cuda_runtime.h>

#define Bsz 2
#define Ssz 256
#define Dsz 768
#define NV  765            // valid spans per batch
#define TOT 32896          // S*(S+1)/2
#define PD  128
#define KSPLIT 3
#define KH  256            // 768 / KSPLIT
#define HS  393216L        // Bsz*Ssz*Dsz

typedef unsigned long long ull;

// Scratch: g_H/g_A layout [ks(3)][z(2)][row(512)][n(768)] (K-split partials)
__device__ float g_H[3 * 2 * Bsz * Ssz * Dsz];
__device__ float g_A[3 * 2 * Bsz * Ssz * Dsz];
__device__ float g_W3[3*Dsz];
__device__ float g_C[4*Dsz];          // 0..2: (W3[w]+b_span)@w_p1+b_p1 ; 3: cpad
__device__ float g_L[1028];
__device__ __align__(16) float g_projpad[PD];
__device__ float g_zero[Dsz];         // statically zero — never written

// ---------------------------------------------------------------------------
__device__ __forceinline__ ull pk2(float x) {
    ull r; asm("mov.b64 %0, {%1, %1};" : "=l"(r) : "f"(x)); return r;
}
__device__ __forceinline__ void fma2(ull& d, ull a, ull b) {
    asm("fma.rn.f32x2 %0, %1, %2, %0;" : "+l"(d) : "l"(a), "l"(b));
}

#define RAW_BYTES (16*65*8 + 16*128*4)   // AsU + Bs

// ---------------------------------------------------------------------------
// SGEMM tile body: 64(M) x 128(N), KT=16, 256 thr, 4x4 f32x2 per thread.
// e in [0,288): nb = e%6, mb = (e/6)%8, zi = e/48 -> z = zi/3, ks = zi%3.
// ---------------------------------------------------------------------------
__device__ __forceinline__ void sgemm_body(
    int e, const float* __restrict__ A,
    const float* __restrict__ Ax1, const float* __restrict__ Ax2, long sAz,
    const float* __restrict__ Bm, long sBz, float* __restrict__ Cc, char* raw)
{
    ull   (*AsU)[65]  = (ull(*)[65])raw;
    float (*Bs)[128]  = (float(*)[128])(raw + 16*65*8);

    const int nb = e % 6, mb = (e / 6) % 8, zi = e / 48;
    const int z = zi / KSPLIT, ks = zi % KSPLIT;
    const int kbase = ks * KH;

    A += (long)z * sAz;
    if (Ax1) { Ax1 += (long)z * sAz; Ax2 += (long)z * sAz; }
    Bm += (long)z * sBz;
    Cc += (long)z * HS + (long)ks * 2 * HS;

    const int tid = threadIdx.x;
    const int tx = tid & 15, ty = tid >> 4;
    const int row0 = mb * 64, col0 = nb * 128;
    const int m_a = tid >> 2, kq = tid & 3;      // A loader
    const int kk0 = tid >> 5, nq0 = tid & 31;    // B loader

    ull acc[4][4] = {};
    float4 pa, pb0, pb1;

    {
        long ab = (long)(row0 + m_a) * Dsz + kbase + kq * 4;
        pa = *(const float4*)(A + ab);
        if (Ax1) {
            float4 q1 = *(const float4*)(Ax1 + ab);
            float4 q2 = *(const float4*)(Ax2 + ab);
            pa.x += q1.x + q2.x; pa.y += q1.y + q2.y;
            pa.z += q1.z + q2.z; pa.w += q1.w + q2.w;
        }
        pb0 = *(const float4*)(Bm + (long)(kbase + kk0) * Dsz + col0 + nq0 * 4);
        pb1 = *(const float4*)(Bm + (long)(kbase + kk0 + 8) * Dsz + col0 + nq0 * 4);
    }

    const int ITERS = KH / 16;   // 16
    for (int it = 0; it < ITERS; it++) {
        __syncthreads();
        AsU[kq * 4 + 0][m_a] = pk2(pa.x);
        AsU[kq * 4 + 1][m_a] = pk2(pa.y);
        AsU[kq * 4 + 2][m_a] = pk2(pa.z);
        AsU[kq * 4 + 3][m_a] = pk2(pa.w);
        ((float4*)&Bs[kk0][0])[nq0]     = pb0;
        ((float4*)&Bs[kk0 + 8][0])[nq0] = pb1;
        __syncthreads();

        if (it + 1 < ITERS) {
            int kb = kbase + (it + 1) * 16;
            long ab = (long)(row0 + m_a) * Dsz + kb + kq * 4;
            pa = *(const float4*)(A + ab);
            if (Ax1) {
                float4 q1 = *(const float4*)(Ax1 + ab);
                float4 q2 = *(const float4*)(Ax2 + ab);
                pa.x += q1.x + q2.x; pa.y += q1.y + q2.y;
                pa.z += q1.z + q2.z; pa.w += q1.w + q2.w;
            }
            pb0 = *(const float4*)(Bm + (long)(kb + kk0) * Dsz + col0 + nq0 * 4);
            pb1 = *(const float4*)(Bm + (long)(kb + kk0 + 8) * Dsz + col0 + nq0 * 4);
        }

        #pragma unroll
        for (int kk = 0; kk < 16; kk++) {
            ull aa[4];
            #pragma unroll
            for (int u = 0; u < 4; u++) aa[u] = AsU[kk][ty + 16 * u];
            const ull* brow = (const ull*)&Bs[kk][0];
            #pragma unroll
            for (int v = 0; v < 4; v++) {
                ull bb = brow[tx + 16 * v];
                #pragma unroll
                for (int u = 0; u < 4; u++) fma2(acc[u][v], aa[u], bb);
            }
        }
    }

    #pragma unroll
    for (int u = 0; u < 4; u++) {
        long rbase = ((long)(row0 + ty + 16 * u) * Dsz + col0) >> 1;
        #pragma unroll
        for (int v = 0; v < 4; v++) {
            float2 r;
            asm("mov.b64 {%0, %1}, %2;" : "=f"(r.x), "=f"(r.y) : "l"(acc[u][v]));
            ((float2*)Cc)[rbase + tx + 16 * v] = r;
        }
    }
}

// ---------------------------------------------------------------------------
// GEMV-64 body: out[n0+nl] = (sum_k src(k) * W[k*ldw + n]) + bias[n]
// 256 thr = 64 n x 4 k-groups of 192.  mode 0: a1 ; 1: a1+a2 ; 2: relu(a1)
// ---------------------------------------------------------------------------
__device__ __forceinline__ void gemv_body(
    const float* __restrict__ a1, const float* __restrict__ a2, int mode,
    const float* __restrict__ W, int ldw,
    const float* __restrict__ bias, float* __restrict__ out,
    int n0, char* raw)
{
    float (*red)[64] = (float(*)[64])raw;
    const int tid = threadIdx.x;
    const int nl = tid & 63, kg = tid >> 6;
    const int n = n0 + nl;
    float s = 0.f;
    const int k0 = kg * 192;
    #pragma unroll 8
    for (int t = 0; t < 192; t++) {
        int k = k0 + t;
        float av = a1[k];
        if (mode == 1) av += a2[k];
        else if (mode == 2) av = fmaxf(av, 0.f);
        s += av * W[(long)k * ldw + n];
    }
    red[kg][nl] = s;
    __syncthreads();
    if (kg == 0)
        out[n] = red[0][nl] + red[1][nl] + red[2][nl] + red[3][nl] + bias[n];
}

// ---------------------------------------------------------------------------
// L1: [0,288) sgemm H ; [288,324) W3 ; [324,336) C-pad row
// ---------------------------------------------------------------------------
__global__ __launch_bounds__(256, 2) void L1_k(
    const float* __restrict__ hidden, const float* __restrict__ width_emb,
    const float* __restrict__ w_span, const float* __restrict__ b_span,
    const float* __restrict__ w_p1, const float* __restrict__ b_p1)
{
    __shared__ __align__(16) char raw[RAW_BYTES];
    int e = blockIdx.x;
    if (e < 288) {
        sgemm_body(e, hidden, nullptr, nullptr, 0L,
                   w_span, (long)Dsz * Dsz, g_H, raw);
    } else if (e < 324) {
        int g = e - 288, m = g / 12, nb = g % 12;
        gemv_body(width_emb + m * Dsz, nullptr, 0,
                  w_span + 2L * Dsz * Dsz, Dsz,
                  g_zero, g_W3 + m * Dsz, nb * 64, raw);
    } else {
        int nb = e - 324;
        gemv_body(b_span, nullptr, 0, w_p1, Dsz, b_p1, g_C + 3 * Dsz,
                  nb * 64, raw);
    }
}

// ---------------------------------------------------------------------------
// L2: [0,288) sgemm A ; [288,324) C rows 0..2 ; [324,326) projpad ;
//     [326,455) dots
// ---------------------------------------------------------------------------
__global__ __launch_bounds__(256, 2) void L2_k(
    const float* __restrict__ w_p1, const float* __restrict__ b_p1,
    const float* __restrict__ b_span, const float* __restrict__ w_cls,
    const float* __restrict__ b_cls, const float* __restrict__ w_p2,
    const float* __restrict__ b_p2)
{
    __shared__ __align__(16) char raw[RAW_BYTES];
    int e = blockIdx.x;
    if (e < 288) {
        sgemm_body(e, g_H, g_H + 2 * HS, g_H + 4 * HS, HS,
                   w_p1, 0L, g_A, raw);
    } else if (e < 324) {
        int g = e - 288, m = g / 12, nb = g % 12;
        gemv_body(g_W3 + m * Dsz, b_span, 1, w_p1, Dsz, b_p1,
                  g_C + m * Dsz, nb * 64, raw);
    } else if (e < 326) {
        int nb = e - 324;
        gemv_body(g_C + 3 * Dsz, nullptr, 2, w_p2, PD, b_p2, g_projpad,
                  nb * 64, raw);
    } else {
        int gw = (e - 326) * 8 + (threadIdx.x >> 5);
        int lane = threadIdx.x & 31;
        if (gw >= 1028) return;
        float s = 0.f;
        if (gw < 1024) {
            int z = gw >> 9, row = gw & 511;
            const float* base = g_H + (long)z * HS + (long)row * Dsz;
            for (int k = lane; k < Dsz; k += 32)
                s += (base[k] + base[2 * HS + k] + base[4 * HS + k]) * w_cls[k];
        } else {
            const float* v = (gw < 1027) ? (g_W3 + (gw - 1024) * Dsz) : b_span;
            for (int k = lane; k < Dsz; k += 32) s += v[k] * w_cls[k];
        }
        #pragma unroll
        for (int o = 16; o > 0; o >>= 1) s += __shfl_down_sync(0xffffffffu, s, o);
        if (lane == 0) g_L[gw] = s + (gw == 1027 ? b_cls[0] : 0.f);
    }
}

// ---------------------------------------------------------------------------
// L3: [0,96) spanproj ; [96,353) logits ; [353,8386) fillpad
// ---------------------------------------------------------------------------
__global__ __launch_bounds__(256, 2) void L3_k(
    const float* __restrict__ w_p2, const float* __restrict__ b_p2,
    float* __restrict__ out)
{
    int e = blockIdx.x;
    if (e < 96) {
        __shared__ float Xs[16][17];
        __shared__ float Ws[16][PD];
        __shared__ int offA1[16], offA2[16], offC[16];
        __shared__ long offOut[16];

        int tid = threadIdx.x;
        int m0 = e * 16;
        if (tid < 16) {
            int msp = m0 + tid;
            int b = 0, i = 0, w = 0;
            bool valid = msp < 2 * NV;
            int kv = 0;
            if (valid) {
                b = msp / NV; kv = msp - b * NV;
                if (kv < 762)      { i = kv / 3; w = kv - 3 * i; }
                else if (kv < 764) { i = 254;   w = kv - 762;   }
                else               { i = 255;   w = 0;          }
            }
            int j = i + w;
            offA1[tid] = (b * Ssz + i) * Dsz;
            offA2[tid] = (int)HS + (b * Ssz + j) * Dsz;
            offC[tid]  = w * Dsz;
            offOut[tid] = valid ? ((long)Bsz * TOT + ((long)b * TOT + kv) * PD) : -1L;
        }
        __syncthreads();

        int tx = tid & 31, ty = tid >> 5;
        float acc[2][4] = {};
        for (int k0 = 0; k0 < Dsz; k0 += 16) {
            {
                int m = tid >> 4, kk = tid & 15;
                long o1 = offA1[m] + k0 + kk, o2 = offA2[m] + k0 + kk;
                float v = g_A[o1] + g_A[o1 + 2 * HS] + g_A[o1 + 4 * HS]
                        + g_A[o2] + g_A[o2 + 2 * HS] + g_A[o2 + 4 * HS]
                        + g_C[offC[m] + k0 + kk];
                Xs[kk][m] = fmaxf(v, 0.f);
            }
            #pragma unroll
            for (int l = 0; l < 8; l++) {
                int idx = tid + l * 256;
                int kk = idx >> 7, n = idx & 127;
                Ws[kk][n] = w_p2[(long)(k0 + kk) * PD + n];
            }
            __syncthreads();
            #pragma unroll
            for (int kk = 0; kk < 16; kk++) {
                float a0 = Xs[kk][ty], a1 = Xs[kk][ty + 8];
                #pragma unroll
                for (int v = 0; v < 4; v++) {
                    float bb = Ws[kk][tx + 32 * v];
                    acc[0][v] += a0 * bb;
                    acc[1][v] += a1 * bb;
                }
            }
            __syncthreads();
        }
        #pragma unroll
        for (int u = 0; u < 2; u++) {
            int m = ty + 8 * u;
            long ob = offOut[m];
            if (ob >= 0) {
                #pragma unroll
                for (int v = 0; v < 4; v++) {
                    int n = tx + 32 * v;
                    out[ob + n] = acc[u][v] + b_p2[n];
                }
            }
        }
    } else if (e < 353) {
        int idx = (e - 96) * 256 + threadIdx.x;
        if (idx >= Bsz * TOT) return;
        int b = idx / TOT, t = idx - b * TOT;
        float v;
        if (t < NV) {
            int i, w;
            if (t < 762)      { i = t / 3; w = t - 3 * i; }
            else if (t < 764) { i = 254;  w = t - 762;   }
            else              { i = 255;  w = 0;         }
            int j = i + w;
            v = g_L[b * Ssz + i] + g_L[512 + b * Ssz + j] + g_L[1024 + w] + g_L[1027];
        } else {
            v = g_L[1027];
        }
        out[idx] = v;
    } else {
        const int PADROWS = TOT - NV;
        long idx = (long)(e - 353) * 256 + threadIdx.x;
        if (idx >= (long)Bsz * PADROWS * 32) return;
        int r = (int)(idx >> 5), c = (int)(idx & 31);
        int b = r / PADROWS;
        int kk = NV + (r - b * PADROWS);
        float4 val = ((const float4*)g_projpad)[c];
        long f4 = (long)(Bsz * TOT) / 4 + ((long)b * TOT + kk) * (PD / 4) + c;
        ((float4*)out)[f4] = val;
    }
}

// ---------------------------------------------------------------------------
extern "C" void kernel_launch(void* const* d_in, const int* in_sizes, int n_in,
                              void* d_out, int out_size)
{
    const float* hidden    = (const float*)d_in[0];
    const float* width_emb = (const float*)d_in[1];
    const float* w_span    = (const float*)d_in[2];
    const float* b_span    = (const float*)d_in[3];
    const float* w_cls     = (const float*)d_in[4];
    const float* b_cls     = (const float*)d_in[5];
    const float* w_p1      = (const float*)d_in[6];
    const float* b_p1      = (const float*)d_in[7];
    const float* w_p2      = (const float*)d_in[8];
    const float* b_p2      = (const float*)d_in[9];
    float* out = (float*)d_out;

    L1_k<<<336, 256>>>(hidden, width_emb, w_span, b_span, w_p1, b_p1);
    L2_k<<<455, 256>>>(w_p1, b_p1, b_span, w_cls, b_cls, w_p2, b_p2);
    L3_k<<<8386, 256>>>(w_p2, b_p2, out);
}